// round 9
// baseline (speedup 1.0000x reference)
#include <cuda_runtime.h>
#include <cstdint>

// Problem shape (fixed by reference setup_inputs)
#define BATCH 8
#define MPRED 100
#define NGT   32
#define HWPIX 65536   // 256*256
#define BN_BYTES (HWPIX * 4)                    // 256 KB per (b,n)
#define F4_PER_BN (HWPIX / 4)                   // 16384
#define GXBLK 4                                  // gather CTAs per (b,n)
#define CTA_BYTES (BN_BYTES / GXBLK)             // 64 KB per gather CTA
#define F4_PER_BLK (F4_PER_BN / GXBLK)           // 4096
#define F4_PER_THR (F4_PER_BLK / 256)            // 16
#define CHUNK_BYTES 16384                        // TMA zero chunk
#define NCHUNK (CTA_BYTES / CHUNK_BYTES)         // 4
#define NMATCH BATCH

// Cross-CTA sync: sentinel per (b,n) carrying gtm+2 (0 = not ready),
// plus consumer counters for replay-safe reset. Zero-initialized.
__device__ int g_sync[BATCH * NGT];
__device__ int g_cnt[BATCH * NGT];

// ---- TMA bulk store helpers -----------------------------------------------
__device__ __forceinline__ uint32_t smem_u32(const void* p) {
    return (uint32_t)__cvta_generic_to_shared(p);
}
__device__ __forceinline__ void tma_store_1d(void* dst, uint32_t src_smem, uint32_t bytes) {
    asm volatile("cp.async.bulk.global.shared::cta.bulk_group [%0], [%1], %2;"
                 :: "l"(dst), "r"(src_smem), "r"(bytes) : "memory");
}
__device__ __forceinline__ void tma_commit() {
    asm volatile("cp.async.bulk.commit_group;" ::: "memory");
}
template <int N>
__device__ __forceinline__ void tma_wait_group() {
    asm volatile("cp.async.bulk.wait_group %0;" :: "n"(N) : "memory");
}
__device__ __forceinline__ void fence_async_shared() {
    asm volatile("fence.proxy.async.shared::cta;" ::: "memory");
}

// ---------------------------------------------------------------------------
// Fused kernel. grid = 8 + B*N*GXBLK = 1032 CTAs, 256 threads.
//   blocks 0..7    : greedy match (publishes sentinel early)
//   blocks 8..1031 : speculative zero-fill via paced TMA bulk stores; once the
//                    match is known: matched -> LDG/STG copy of all 64 KB,
//                    unmatched -> blast remaining TMA zero chunks.
// ---------------------------------------------------------------------------
__global__ void __launch_bounds__(256, 7) fused_kernel(
                             const float* __restrict__ pred_boxes,  // [B,M,4]
                             const float* __restrict__ gt_boxes,    // [B,N,4]
                             const float* __restrict__ pred_scores, // [B,M]
                             const float* __restrict__ pred_masks,  // [B,M,H,W]
                             const float* __restrict__ mask_score,  // [B,M]
                             float* __restrict__ out)
{
    const int tid = threadIdx.x;

    if (blockIdx.x < NMATCH) {
        // =================== MATCH PATH ===================
        const int b    = blockIdx.x;
        const int wid  = tid >> 5;
        const int lane = tid & 31;      // lane = GT index

        __shared__ float4 s_pbox[MPRED];
        __shared__ float  s_score[MPRED];
        __shared__ float  s_iou[MPRED * NGT];
        __shared__ int    s_hit[128];
        __shared__ int    s_hits[MPRED];
        __shared__ int    s_sorted[MPRED];
        __shared__ int    s_nhits;

        const float4* pb4 = reinterpret_cast<const float4*>(pred_boxes + b * MPRED * 4);
        const float*  ps  = pred_scores + b * MPRED;
        if (tid < MPRED) { s_pbox[tid] = pb4[tid]; s_score[tid] = ps[tid]; }
        if (tid < 128) s_hit[tid] = 0;
        __syncthreads();

        const float* gb = gt_boxes + (b * NGT + lane) * 4;
        const float g0 = gb[0], g1 = gb[1], g2 = gb[2], g3 = gb[3];
        const float area2 = (g2 - g0) * (g3 - g1);

        // Phase A: IoU matrix + per-pred hit flags (8 warps in parallel)
        for (int p = wid; p < MPRED; p += 8) {
            const float4 pbx = s_pbox[p];
            const float area1 = (pbx.z - pbx.x) * (pbx.w - pbx.y);
            const float lx = fmaxf(pbx.x, g0), ly = fmaxf(pbx.y, g1);
            const float rx = fminf(pbx.z, g2), ry = fminf(pbx.w, g3);
            const float w  = fmaxf(rx - lx, 0.0f);
            const float h  = fmaxf(ry - ly, 0.0f);
            const float inter = w * h;
            const float iou = __fdividef(inter, area1 + area2 - inter);
            s_iou[p * NGT + lane] = iou;
            const unsigned bal = __ballot_sync(0xffffffffu, iou >= 0.5f);
            if (lane == 0) s_hit[p] = (bal != 0u) && (s_score[p] >= 0.0f);
        }
        __syncthreads();

        if (wid == 0) {
            // compaction via ballots + prefix popcount
            int nh = 0;
            #pragma unroll
            for (int k = 0; k < 4; k++) {
                const int p = k * 32 + lane;
                const int f = (p < MPRED) ? s_hit[p] : 0;
                const unsigned bal = __ballot_sync(0xffffffffu, f != 0);
                if (f) s_hits[nh + __popc(bal & ((1u << lane) - 1u))] = p;
                nh += __popc(bal);
            }
            if (lane == 0) s_nhits = nh;
            __syncwarp();
            const int K = s_nhits;

            // stable descending rank-sort (== jnp.argsort(-scores) on hit set)
            for (int t = lane; t < K; t += 32) {
                const int   hi = s_hits[t];
                const float si = s_score[hi];
                int rank = 0;
                for (int u = 0; u < K; u++) {
                    const int   hu = s_hits[u];
                    const float su = s_score[hu];
                    rank += (su > si) || (su == si && hu < hi);
                }
                s_sorted[rank] = hi;
            }
            __syncwarp();

            // serial greedy scan
            int   gtm  = -1;
            float biou = 0.0f;
            for (int t = 0; t < K; t++) {
                const int   i   = s_sorted[t];
                const float iou = s_iou[i * NGT + lane];
                // Faithful to reference: gt available iff gtm <= 0 (intentional "bug")
                const bool  valid = (gtm <= 0) && (iou >= 0.5f);
                const unsigned key  = valid ? __float_as_uint(iou) : 0u;
                const unsigned kmax = __reduce_max_sync(0xffffffffu, key);
                if (kmax != 0u) {
                    const unsigned bal = __ballot_sync(0xffffffffu, key == kmax);
                    const int m = __ffs(bal) - 1;   // lowest lane = jnp.argmax
                    if (lane == m) { gtm = i; biou = iou; }
                }
            }

            // Publish FIRST (payload in flag, single word, nonzero)
            const int bn = b * NGT + lane;
            atomicExch(&g_sync[bn], gtm + 2);

            // Tail scalar outputs (off the critical path)
            float* flags_out = out + (long long)BATCH * NGT * HWPIX;
            float* gtm_out   = flags_out + BATCH * NGT;
            float* biou_out  = gtm_out   + BATCH * NGT;
            flags_out[bn] = (gtm > -1) ? mask_score[b * MPRED + gtm] : 0.0f;
            gtm_out[bn]   = (float)gtm;
            biou_out[bn]  = biou;
        }
    } else {
        // =================== GATHER PATH ===================
        const int u  = blockIdx.x - NMATCH;   // 0..1023
        const int bn = u >> 2;
        const int b  = bn >> 5;
        const int xq = u & 3;                 // quarter index

        __shared__ alignas(128) float4 s_zero[CHUNK_BYTES / 16];  // 16 KB of zeros
        __shared__ int sh_g;                  // -2 = unknown, else gtm

        // Zero the smem tile (256 thr x 4 float4)
        const float4 z = make_float4(0.0f, 0.0f, 0.0f, 0.0f);
        #pragma unroll
        for (int k = 0; k < CHUNK_BYTES / 16 / 256; k++)
            s_zero[k * 256 + tid] = z;
        __syncthreads();

        volatile int* sy = (volatile int*)&g_sync[bn];
        char* dst = (char*)out + (long long)bn * BN_BYTES + (long long)xq * CTA_BYTES;

        int g = -2;
        if (tid == 0) {
            fence_async_shared();   // STS zeros -> async proxy visibility
            const uint32_t zb = smem_u32(&s_zero[0]);

            // first poll
            { const int v = *sy; if (v) g = v - 2; }

            // Speculation loop: paced TMA zero stores; poll hidden under wait.
            int c = 0;
            while (g == -2 && c < NCHUNK) {
                const int v = *sy;                       // in flight during store
                tma_store_1d(dst + (long long)c * CHUNK_BYTES, zb, CHUNK_BYTES);
                tma_commit();
                tma_wait_group<0>();                     // pacing (~chunk epoch)
                c++;
                if (v) g = v - 2;
            }
            // Still unknown and everything zeroed: spin.
            if (g == -2) {
                int v = *sy;
                while (v == 0) { __nanosleep(128); v = *sy; }
                g = v - 2;
            }
            if (g <= -1) {
                // Unmatched: blast remaining zero chunks.
                for (; c < NCHUNK; c++) {
                    tma_store_1d(dst + (long long)c * CHUNK_BYTES, zb, CHUNK_BYTES);
                }
                tma_commit();
                tma_wait_group<0>();
                g = -1;
            }
            // Matched: TMA zero stores already drained (wait_group in loop).
            sh_g = g;
        }
        __syncthreads();
        g = sh_g;

        if (g > -1) {
            // Matched: copy the whole 64 KB (covers speculated chunks too; TMA
            // stores drained before the barrier, so STG lands last).
            const int base = xq * F4_PER_BLK + tid;
            float4* o = reinterpret_cast<float4*>(out) + (long long)bn * F4_PER_BN + base;
            const float4* src = reinterpret_cast<const float4*>(pred_masks)
                              + (long long)(b * MPRED + g) * F4_PER_BN + base;
            #pragma unroll
            for (int q = 0; q < F4_PER_THR / 4; q++) {   // 4 batches of MLP-4
                float4 v0 = src[(q * 4 + 0) * 256];
                float4 v1 = src[(q * 4 + 1) * 256];
                float4 v2 = src[(q * 4 + 2) * 256];
                float4 v3 = src[(q * 4 + 3) * 256];
                o[(q * 4 + 0) * 256] = v0;
                o[(q * 4 + 1) * 256] = v1;
                o[(q * 4 + 2) * 256] = v2;
                o[(q * 4 + 3) * 256] = v3;
            }
        }

        // Replay-safe reset: 4th consumer CTA clears sentinel + counter.
        __syncthreads();
        if (tid == 0) {
            const int old = atomicAdd(&g_cnt[bn], 1);
            if (old == 3) {
                *(volatile int*)&g_cnt[bn]  = 0;
                *(volatile int*)&g_sync[bn] = 0;
            }
        }
    }
}

// ---------------------------------------------------------------------------
extern "C" void kernel_launch(void* const* d_in, const int* in_sizes, int n_in,
                              void* d_out, int out_size)
{
    const float* pred_boxes  = (const float*)d_in[0];
    const float* gt_boxes    = (const float*)d_in[1];
    const float* pred_scores = (const float*)d_in[2];
    const float* pred_masks  = (const float*)d_in[3];
    const float* mask_score  = (const float*)d_in[4];
    float* out = (float*)d_out;

    const int nblk = NMATCH + BATCH * NGT * GXBLK;   // 8 + 1024 = 1032
    fused_kernel<<<nblk, 256>>>(pred_boxes, gt_boxes, pred_scores,
                                pred_masks, mask_score, out);
}